// round 8
// baseline (speedup 1.0000x reference)
#include <cuda_runtime.h>
#include <math.h>

#define NCTA 144      // 112 A1 CTAs + 32 B CTAs
#define NA1  112
#define EPSF 1e-8f

__device__ float d_XP[256*2048*32];     // [t][row][b]
__device__ float d_XinT[256*256*32];    // [t][i][b]
__device__ float d_WrecT[576*2048];     // [k][row]
__device__ float d_WxT[256*2048];       // [i][row]
__device__ float d_WheadT[512*272];     // [k][o] padded
__device__ float d_WoutT[576*256];      // [k][o]
__device__ float d_Part[7*2048*32];     // [kc][row][b]
__device__ float d_XT[576*32];          // [k][b] 0..511=h, 512..575=r
__device__ float d_HR[256*576*32];      // [t][k][b]
__device__ unsigned d_barcnt;

__device__ __forceinline__ float sigmf(float x){ return 1.f/(1.f+expf(-x)); }
__device__ __forceinline__ float softplusf(float x){ return fmaxf(x,0.f)+log1pf(expf(-fabsf(x))); }

__device__ __forceinline__ void gridbar(unsigned target){
    __syncthreads();
    __threadfence();
    if(threadIdx.x==0){
        atomicAdd(&d_barcnt,1u);
        while(*(volatile unsigned*)&d_barcnt < target){}
        __threadfence();
    }
    __syncthreads();
}

__global__ void prep_kernel(const float* __restrict__ W_ih,const float* __restrict__ W_hh,
                            const float* __restrict__ W_head,const float* __restrict__ W_out){
    if(blockIdx.x==0&&threadIdx.x==0) d_barcnt=0u;
    int tid=blockIdx.x*blockDim.x+threadIdx.x, nt=gridDim.x*blockDim.x;
    for(int i=tid;i<576*2048;i+=nt){
        int k=i>>11,row=i&2047;
        d_WrecT[i]=(k<512)?W_hh[row*512+k]:W_ih[row*320+256+(k-512)];
    }
    for(int i=tid;i<256*2048;i+=nt){
        int k=i>>11,row=i&2047;
        d_WxT[i]=W_ih[row*320+k];
    }
    for(int i=tid;i<512*272;i+=nt){
        int j=i/272,o=i%272;
        d_WheadT[i]=(o<268)?W_head[o*512+j]:0.f;
    }
    for(int i=tid;i<576*256;i+=nt){
        int k=i>>8,o=i&255;
        d_WoutT[i]=W_out[o*576+k];
    }
}

__global__ void tin_kernel(const float* __restrict__ x){
    __shared__ float sm[32][33];
    int it=blockIdx.x,t=blockIdx.y;
    int lane=threadIdx.x&31,r=threadIdx.x>>5,i0=it*32;
#pragma unroll
    for(int q=0;q<4;q++){ int b=r+q*8; sm[lane][b]=x[(b*256+t)*256+i0+lane]; }
    __syncthreads();
#pragma unroll
    for(int q=0;q<4;q++){ int i=r+q*8; d_XinT[(t*256+i0+i)*32+lane]=sm[i][lane]; }
}

__global__ __launch_bounds__(256) void xp_gemm_kernel(){
    __shared__ __align__(16) float Ws[64*128];
    __shared__ __align__(16) float Xs[64*32];
    int rb=blockIdx.x,t=blockIdx.y,tid=threadIdx.x;
    int ty=tid>>3,tx=tid&7;
    float acc[4][4]={};
    for(int kc=0;kc<4;kc++){
        for(int idx=tid;idx<64*32;idx+=256){
            int k=idx>>5,r4=idx&31;
            *(float4*)&Ws[k*128+r4*4]=*(const float4*)&d_WxT[(kc*64+k)*2048+rb*128+r4*4];
        }
        for(int idx=tid;idx<64*8;idx+=256){
            int k=idx>>3,b4=idx&7;
            *(float4*)&Xs[k*32+b4*4]=*(const float4*)&d_XinT[(t*256+kc*64+k)*32+b4*4];
        }
        __syncthreads();
#pragma unroll 8
        for(int k=0;k<64;k++){
            float4 wv=*(float4*)&Ws[k*128+ty*4];
            float4 xv=*(float4*)&Xs[k*32+tx*4];
            acc[0][0]+=wv.x*xv.x;acc[0][1]+=wv.x*xv.y;acc[0][2]+=wv.x*xv.z;acc[0][3]+=wv.x*xv.w;
            acc[1][0]+=wv.y*xv.x;acc[1][1]+=wv.y*xv.y;acc[1][2]+=wv.y*xv.z;acc[1][3]+=wv.y*xv.w;
            acc[2][0]+=wv.z*xv.x;acc[2][1]+=wv.z*xv.y;acc[2][2]+=wv.z*xv.z;acc[2][3]+=wv.z*xv.w;
            acc[3][0]+=wv.w*xv.x;acc[3][1]+=wv.w*xv.y;acc[3][2]+=wv.w*xv.z;acc[3][3]+=wv.w*xv.w;
        }
        __syncthreads();
    }
    int row0=rb*128+ty*4;
#pragma unroll
    for(int i=0;i<4;i++)
        *(float4*)&d_XP[(t*2048+row0+i)*32+tx*4]=make_float4(acc[i][0],acc[i][1],acc[i][2],acc[i][3]);
}

__global__ __launch_bounds__(256) void ntm_loop_kernel(const float* __restrict__ b_lstm,
                                                       const float* __restrict__ b_head){
    union __align__(16) Smem{
        struct{ float Ws[74*128]; float Xs[74*32]; } a1;                  // A1 CTAs only
        struct{
            float Ms[128*65];                                            // persistent M
            float hs[512]; float ps[272];
            float kr[64],kw[64],er[64],aw[64];
            float wr[128],ww[128],wcr[128],wcw[128];
            float redbuf[8]; float sc[16]; float minv[128];
            float sred[4*256];
        } b2;                                                            // B CTAs only
    };
    __shared__ Smem su;
    const int g=blockIdx.x,tid=threadIdx.x;
    unsigned nb=0;
    const bool isB=(g>=NA1);
    const int  b  = g-NA1;           // batch for B CTAs
    const int  rb = g/7, kc = g%7;   // for A1 CTAs
    const int  ks = kc*74;
    const int  len=(kc==6)?68:74;
    const int  ty=tid>>3, tx=tid&7;

    // ---- init ----
    {
        int gt=g*256+tid; const int nt=NCTA*256;
        for(int i=gt;i<576*32;i+=nt) d_XT[i]=0.f;
        for(int i=gt;i<7*2048*32;i+=nt) d_Part[i]=0.f;
    }
    if(isB){
        for(int i=tid;i<8192;i+=256) su.b2.Ms[(i>>6)*65+(i&63)]=0.01f;
        if(tid<128){ float v=(tid==0)?1.f:0.f; su.b2.wr[tid]=v; su.b2.ww[tid]=v; }
    }else{
        // load persistent A1 weight tile once
        for(int idx=tid;idx<len*32;idx+=256){
            int k=idx>>5,r4=idx&31;
            *(float4*)&su.a1.Ws[k*128+r4*4]=*(const float4*)&d_WrecT[(ks+k)*2048+rb*128+r4*4];
        }
    }
    float creg[4]={0.f,0.f,0.f,0.f}; // LSTM cell state: thread (jo,b) of CTA g<128 owns j=g*4+jo... 1 value
    float cst=0.f;
    nb++; gridbar(nb*NCTA);

    for(int t=0;t<256;t++){
        // ===== phase 1 (A2): gates = Σ h-partials + W_r·r + XP + bias ; LSTM =====
        if(g<128 && tid<128){
            int jo=tid>>5, bb=tid&31, j=g*4+jo;
            float s0=b_lstm[j      ]+d_XP[(t*2048+j      )*32+bb];
            float s1=b_lstm[j+ 512 ]+d_XP[(t*2048+j+ 512 )*32+bb];
            float s2=b_lstm[j+1024 ]+d_XP[(t*2048+j+1024 )*32+bb];
            float s3=b_lstm[j+1536 ]+d_XP[(t*2048+j+1536 )*32+bb];
#pragma unroll
            for(int kk=0;kk<7;kk++){
                s0+=d_Part[(kk*2048+j      )*32+bb];
                s1+=d_Part[(kk*2048+j+ 512 )*32+bb];
                s2+=d_Part[(kk*2048+j+1024 )*32+bb];
                s3+=d_Part[(kk*2048+j+1536 )*32+bb];
            }
#pragma unroll 4
            for(int c=0;c<64;c++){
                float rv=d_XT[(512+c)*32+bb];
                const float* wp=&d_WrecT[(512+c)*2048+j];
                s0+=wp[0]*rv; s1+=wp[512]*rv; s2+=wp[1024]*rv; s3+=wp[1536]*rv;
            }
            float cnew=sigmf(s1)*cst+sigmf(s0)*tanhf(s2);
            float h=sigmf(s3)*tanhf(cnew);
            cst=cnew;
            d_XT[j*32+bb]=h;
            d_HR[(t*576+j)*32+bb]=h;
        }
        nb++; gridbar(nb*NCTA);

        // ===== phase 2 =====
        if(!isB){
            // ---- A1: h-part recurrent GEMM partials for step t+1 ----
            for(int idx=tid;idx<len*8;idx+=256){
                int k=idx>>3,b4=idx&7;
                *(float4*)&su.a1.Xs[k*32+b4*4]=*(const float4*)&d_XT[(ks+k)*32+b4*4];
            }
            __syncthreads();
            float acc[4][4]={};
#pragma unroll 2
            for(int k=0;k<len;k++){
                float4 wv=*(float4*)&su.a1.Ws[k*128+ty*4];
                float4 xv=*(float4*)&su.a1.Xs[k*32+tx*4];
                acc[0][0]+=wv.x*xv.x;acc[0][1]+=wv.x*xv.y;acc[0][2]+=wv.x*xv.z;acc[0][3]+=wv.x*xv.w;
                acc[1][0]+=wv.y*xv.x;acc[1][1]+=wv.y*xv.y;acc[1][2]+=wv.y*xv.z;acc[1][3]+=wv.y*xv.w;
                acc[2][0]+=wv.z*xv.x;acc[2][1]+=wv.z*xv.y;acc[2][2]+=wv.z*xv.z;acc[2][3]+=wv.z*xv.w;
                acc[3][0]+=wv.w*xv.x;acc[3][1]+=wv.w*xv.y;acc[3][2]+=wv.w*xv.z;acc[3][3]+=wv.w*xv.w;
            }
            int row0=rb*128+ty*4;
#pragma unroll
            for(int i=0;i<4;i++)
                *(float4*)&d_Part[(kc*2048+row0+i)*32+tx*4]=make_float4(acc[i][0],acc[i][1],acc[i][2],acc[i][3]);
            __syncthreads();
        }else{
            // ---- B: head GEMM + addressing + M update + read (batch b) ----
            su.b2.hs[tid]     =d_XT[ tid      *32+b];
            su.b2.hs[tid+256] =d_XT[(tid+256)*32+b];
            __syncthreads();
            {   // o 0..255 : 4 outputs x 4 k-splits
                int kg=tid>>6, og=tid&63;
                float4 acc=make_float4(0.f,0.f,0.f,0.f);
                int k0=kg*128;
#pragma unroll 4
                for(int k=k0;k<k0+128;k++){
                    float4 wv=*(const float4*)&d_WheadT[k*272+og*4];
                    float hv=su.b2.hs[k];
                    acc.x+=wv.x*hv; acc.y+=wv.y*hv; acc.z+=wv.z*hv; acc.w+=wv.w*hv;
                }
                *(float4*)&su.b2.sred[kg*256+og*4]=acc;
            }
            if(tid<3){ // o 256..267
                int o4=256+tid*4;
                float4 acc=make_float4(0.f,0.f,0.f,0.f);
#pragma unroll 4
                for(int k=0;k<512;k++){
                    float4 wv=*(const float4*)&d_WheadT[k*272+o4];
                    float hv=su.b2.hs[k];
                    acc.x+=wv.x*hv; acc.y+=wv.y*hv; acc.z+=wv.z*hv; acc.w+=wv.w*hv;
                }
                su.b2.ps[o4  ]=acc.x+b_head[o4  ];
                su.b2.ps[o4+1]=acc.y+b_head[o4+1];
                su.b2.ps[o4+2]=acc.z+b_head[o4+2];
                su.b2.ps[o4+3]=acc.w+b_head[o4+3];
            }
            __syncthreads();
            su.b2.ps[tid]=su.b2.sred[tid]+su.b2.sred[256+tid]+su.b2.sred[512+tid]+su.b2.sred[768+tid]
                          +b_head[tid];
            __syncthreads();

            // scalars
            if(tid==0){
                su.b2.sc[0]=softplusf(su.b2.ps[64]);
                su.b2.sc[1]=sigmf(su.b2.ps[65]);
                float m=fmaxf(su.b2.ps[66],fmaxf(su.b2.ps[67],su.b2.ps[68]));
                float e0=expf(su.b2.ps[66]-m),e1=expf(su.b2.ps[67]-m),e2=expf(su.b2.ps[68]-m);
                float s=e0+e1+e2;
                su.b2.sc[2]=e0/s;su.b2.sc[3]=e1/s;su.b2.sc[4]=e2/s;
                su.b2.sc[5]=1.f+softplusf(su.b2.ps[69]);
            }
            if(tid==32){
                su.b2.sc[6]=softplusf(su.b2.ps[134]);
                su.b2.sc[7]=sigmf(su.b2.ps[135]);
                float m=fmaxf(su.b2.ps[136],fmaxf(su.b2.ps[137],su.b2.ps[138]));
                float e0=expf(su.b2.ps[136]-m),e1=expf(su.b2.ps[137]-m),e2=expf(su.b2.ps[138]-m);
                float s=e0+e1+e2;
                su.b2.sc[8]=e0/s;su.b2.sc[9]=e1/s;su.b2.sc[10]=e2/s;
                su.b2.sc[11]=1.f+softplusf(su.b2.ps[139]);
            }
            if(tid==64){
                float s=0.f;
                for(int c=0;c<64;c++){float v=su.b2.ps[c];s+=v*v;}
                su.b2.sc[12]=sqrtf(s)+EPSF;
            }
            if(tid==96){
                float s=0.f;
                for(int c=0;c<64;c++){float v=su.b2.ps[70+c];s+=v*v;}
                su.b2.sc[13]=sqrtf(s)+EPSF;
            }
            if(tid>=128&&tid<192){
                int c=tid-128;
                su.b2.kr[c]=su.b2.ps[c];
                su.b2.kw[c]=su.b2.ps[70+c];
                su.b2.er[c]=sigmf(su.b2.ps[140+c]);
                su.b2.aw[c]=su.b2.ps[204+c];
            }
            __syncthreads();

            const int n=tid&127;
            float* Ms=su.b2.Ms;
            float myv;
            {
                const float* mr=&Ms[n*65];
                if(tid<128){
                    float m2=0.f,dr=0.f;
                    for(int c=0;c<64;c++){float mv=mr[c];m2+=mv*mv;dr+=mv*su.b2.kr[c];}
                    float inv=1.f/(sqrtf(m2)+EPSF);
                    su.b2.minv[n]=inv;
                    myv=su.b2.sc[0]*dr*inv/su.b2.sc[12];
                }else{
                    float dw=0.f;
                    for(int c=0;c<64;c++) dw+=mr[c]*su.b2.kw[c];
                    myv=dw;
                }
            }
            __syncthreads();
            if(tid>=128) myv=su.b2.sc[6]*myv*su.b2.minv[n]/su.b2.sc[13];

            float m=myv;
#pragma unroll
            for(int o=16;o>0;o>>=1) m=fmaxf(m,__shfl_xor_sync(0xffffffffu,m,o));
            if((tid&31)==0) su.b2.redbuf[tid>>5]=m;
            __syncthreads();
            float h0=fmaxf(fmaxf(su.b2.redbuf[0],su.b2.redbuf[1]),fmaxf(su.b2.redbuf[2],su.b2.redbuf[3]));
            float h1=fmaxf(fmaxf(su.b2.redbuf[4],su.b2.redbuf[5]),fmaxf(su.b2.redbuf[6],su.b2.redbuf[7]));
            __syncthreads();
            float ex=expf(myv-((tid<128)?h0:h1));
            float sm2=ex;
#pragma unroll
            for(int o=16;o>0;o>>=1) sm2+=__shfl_xor_sync(0xffffffffu,sm2,o);
            if((tid&31)==0) su.b2.redbuf[tid>>5]=sm2;
            __syncthreads();
            float s0h=su.b2.redbuf[0]+su.b2.redbuf[1]+su.b2.redbuf[2]+su.b2.redbuf[3];
            float s1h=su.b2.redbuf[4]+su.b2.redbuf[5]+su.b2.redbuf[6]+su.b2.redbuf[7];
            float wc=ex/((tid<128)?s0h:s1h);

            float wprev=(tid<128)?su.b2.wr[n]:su.b2.ww[n];
            float ggate=(tid<128)?su.b2.sc[1]:su.b2.sc[7];
            float wg=ggate*wc+(1.f-ggate)*wprev;
            __syncthreads();
            if(tid<128) su.b2.wcr[n]=wg; else su.b2.wcw[n]=wg;
            __syncthreads();

            float sA,sB,sC,gam;
            if(tid<128){sA=su.b2.sc[2];sB=su.b2.sc[3];sC=su.b2.sc[4];gam=su.b2.sc[5];}
            else       {sA=su.b2.sc[8];sB=su.b2.sc[9];sC=su.b2.sc[10];gam=su.b2.sc[11];}
            const float* WArr=(tid<128)?su.b2.wcr:su.b2.wcw;
            float wsv=sA*WArr[(n+1)&127]+sB*WArr[n]+sC*WArr[(n+127)&127];
            float wp=powf(wsv+EPSF,gam);
            __syncthreads();
            float sp=wp;
#pragma unroll
            for(int o=16;o>0;o>>=1) sp+=__shfl_xor_sync(0xffffffffu,sp,o);
            if((tid&31)==0) su.b2.redbuf[tid>>5]=sp;
            __syncthreads();
            float p0=su.b2.redbuf[0]+su.b2.redbuf[1]+su.b2.redbuf[2]+su.b2.redbuf[3];
            float p1=su.b2.redbuf[4]+su.b2.redbuf[5]+su.b2.redbuf[6]+su.b2.redbuf[7];
            float wfin=wp/((tid<128)?p0:p1);
            if(tid<128){su.b2.wcr[n]=wfin;su.b2.wr[n]=wfin;}
            else       {su.b2.wcw[n]=wfin;su.b2.ww[n]=wfin;}
            __syncthreads();

            for(int i=tid;i<8192;i+=256){
                int n2=i>>6,c=i&63;
                float wwn=su.b2.wcw[n2];
                float mval=Ms[n2*65+c];
                Ms[n2*65+c]=mval*(1.f-wwn*su.b2.er[c])+wwn*su.b2.aw[c];
            }
            __syncthreads();
            if(tid<64){
                int c=tid;
                float acc=0.f;
                for(int n2=0;n2<128;n2++) acc+=su.b2.wcr[n2]*Ms[n2*65+c];
                d_XT[(512+c)*32+b]=acc;
                d_HR[(t*576+512+c)*32+b]=acc;
            }
            __syncthreads();
        }
        nb++; gridbar(nb*NCTA);
    }
    (void)creg;
}

__global__ __launch_bounds__(256) void out_gemm_kernel(const float* __restrict__ b_out,
                                                       float* __restrict__ out){
    __shared__ __align__(16) float Ws[32*256];
    __shared__ __align__(16) float Xs[32*32];
    int t=blockIdx.x,tid=threadIdx.x;
    int og=tid>>2,bg=tid&3;
    float acc[8][4]={};
    for(int kc=0;kc<18;kc++){
        for(int idx=tid;idx<32*64;idx+=256){
            int k=idx>>6,o4=idx&63;
            *(float4*)&Ws[k*256+o4*4]=*(const float4*)&d_WoutT[(kc*32+k)*256+o4*4];
        }
        for(int idx=tid;idx<32*8;idx+=256){
            int k=idx>>3,b4=idx&7;
            *(float4*)&Xs[k*32+b4*4]=*(const float4*)&d_HR[(t*576+kc*32+k)*32+b4*4];
        }
        __syncthreads();
#pragma unroll 8
        for(int k=0;k<32;k++){
            float4 wv=*(float4*)&Ws[k*256+og*4];
            float4 x0=*(float4*)&Xs[k*32+bg*8];
            float4 x1=*(float4*)&Xs[k*32+bg*8+4];
            acc[0][0]+=x0.x*wv.x;acc[0][1]+=x0.x*wv.y;acc[0][2]+=x0.x*wv.z;acc[0][3]+=x0.x*wv.w;
            acc[1][0]+=x0.y*wv.x;acc[1][1]+=x0.y*wv.y;acc[1][2]+=x0.y*wv.z;acc[1][3]+=x0.y*wv.w;
            acc[2][0]+=x0.z*wv.x;acc[2][1]+=x0.z*wv.y;acc[2][2]+=x0.z*wv.z;acc[2][3]+=x0.z*wv.w;
            acc[3][0]+=x0.w*wv.x;acc[3][1]+=x0.w*wv.y;acc[3][2]+=x0.w*wv.z;acc[3][3]+=x0.w*wv.w;
            acc[4][0]+=x1.x*wv.x;acc[4][1]+=x1.x*wv.y;acc[4][2]+=x1.x*wv.z;acc[4][3]+=x1.x*wv.w;
            acc[5][0]+=x1.y*wv.x;acc[5][1]+=x1.y*wv.y;acc[5][2]+=x1.y*wv.z;acc[5][3]+=x1.y*wv.w;
            acc[6][0]+=x1.z*wv.x;acc[6][1]+=x1.z*wv.y;acc[6][2]+=x1.z*wv.z;acc[6][3]+=x1.z*wv.w;
            acc[7][0]+=x1.w*wv.x;acc[7][1]+=x1.w*wv.y;acc[7][2]+=x1.w*wv.z;acc[7][3]+=x1.w*wv.w;
        }
        __syncthreads();
    }
    int o0=og*4;
    float4 bias=*(const float4*)&b_out[o0];
#pragma unroll
    for(int bb=0;bb<8;bb++){
        int b=bg*8+bb;
        *(float4*)&out[(b*256+t)*256+o0]=make_float4(acc[bb][0]+bias.x,acc[bb][1]+bias.y,
                                                     acc[bb][2]+bias.z,acc[bb][3]+bias.w);
    }
}

extern "C" void kernel_launch(void* const* d_in, const int* in_sizes, int n_in,
                              void* d_out, int out_size){
    const float* x     =(const float*)d_in[0];
    const float* W_ih  =(const float*)d_in[1];
    const float* W_hh  =(const float*)d_in[2];
    const float* b_lstm=(const float*)d_in[3];
    const float* W_head=(const float*)d_in[4];
    const float* b_head=(const float*)d_in[5];
    const float* W_out =(const float*)d_in[6];
    const float* b_out =(const float*)d_in[7];
    float* out=(float*)d_out;

    prep_kernel<<<148,256>>>(W_ih,W_hh,W_head,W_out);
    tin_kernel<<<dim3(8,256),256>>>(x);
    xp_gemm_kernel<<<dim3(16,256),256>>>();
    ntm_loop_kernel<<<NCTA,256>>>(b_lstm,b_head);
    out_gemm_kernel<<<256,256>>>(b_out,out);
}

// round 9
// speedup vs baseline: 2.0525x; 2.0525x over previous
#include <cuda_runtime.h>
#include <math.h>

#define NBLK 128
#define EPSF 1e-8f

// smem layout (dynamic, one CTA/SM):
//   [0      , 36864) Ws   72x128  (A1 weights, loaded once)
//   [36864  , 46080) Xs   72x32   (A1 activations, per step)
//   [46080  , 79360) Ms   128x65  (persistent M, B2 CTAs)
//   [79360  , 79872) wr   128     (persistent)
//   [79872  , 80384) ww   128     (persistent)
//   [80384  , 84128) scratch: A2 gs[512] | B1 sred[768] | B2 transients (936 f)
#define SMEM_BYTES 84992

__device__ float d_XP[256*2048*32];     // [t][row][b]
__device__ float d_XinT[256*256*32];    // [t][i][b]
__device__ float d_WrecT[576*2048];     // [k][row]
__device__ float d_WxT[256*2048];       // [i][row]
__device__ float d_WheadT[512*272];     // [j][o] padded
__device__ float d_WoutT[576*256];      // [k][o]
__device__ float d_Part[8*2048*32];     // [kc][row][b]
__device__ float d_XT[576*32];          // [k][b] 0..511=h, 512..575=r
__device__ float d_cT[512*32];          // [j][b]
__device__ float d_HR[256*576*32];      // [t][k][b]
__device__ float d_P[272*32];           // [o][b]
__device__ unsigned d_barcnt;

__device__ __forceinline__ float sigmf(float x){ return 1.f/(1.f+expf(-x)); }
__device__ __forceinline__ float softplusf(float x){ return fmaxf(x,0.f)+log1pf(expf(-fabsf(x))); }

__device__ __forceinline__ void gridbar(unsigned target){
    __syncthreads();
    __threadfence();
    if(threadIdx.x==0){
        atomicAdd(&d_barcnt,1u);
        while(*(volatile unsigned*)&d_barcnt < target){ __nanosleep(64); }
        __threadfence();
    }
    __syncthreads();
}

__global__ void prep_kernel(const float* __restrict__ W_ih,const float* __restrict__ W_hh,
                            const float* __restrict__ W_head,const float* __restrict__ W_out){
    if(blockIdx.x==0&&threadIdx.x==0) d_barcnt=0u;
    int tid=blockIdx.x*blockDim.x+threadIdx.x, nt=gridDim.x*blockDim.x;
    for(int i=tid;i<576*2048;i+=nt){
        int k=i>>11,row=i&2047;
        d_WrecT[i]=(k<512)?W_hh[row*512+k]:W_ih[row*320+256+(k-512)];
    }
    for(int i=tid;i<256*2048;i+=nt){
        int k=i>>11,row=i&2047;
        d_WxT[i]=W_ih[row*320+k];
    }
    for(int i=tid;i<512*272;i+=nt){
        int j=i/272,o=i%272;
        d_WheadT[i]=(o<268)?W_head[o*512+j]:0.f;
    }
    for(int i=tid;i<576*256;i+=nt){
        int k=i>>8,o=i&255;
        d_WoutT[i]=W_out[o*576+k];
    }
}

__global__ void tin_kernel(const float* __restrict__ x){
    __shared__ float sm[32][33];
    int it=blockIdx.x,t=blockIdx.y;
    int lane=threadIdx.x&31,r=threadIdx.x>>5,i0=it*32;
#pragma unroll
    for(int q=0;q<4;q++){ int b=r+q*8; sm[lane][b]=x[(b*256+t)*256+i0+lane]; }
    __syncthreads();
#pragma unroll
    for(int q=0;q<4;q++){ int i=r+q*8; d_XinT[(t*256+i0+i)*32+lane]=sm[i][lane]; }
}

__global__ __launch_bounds__(256) void xp_gemm_kernel(){
    __shared__ __align__(16) float Ws[64*128];
    __shared__ __align__(16) float Xs[64*32];
    int rb=blockIdx.x,t=blockIdx.y,tid=threadIdx.x;
    int ty=tid>>3,tx=tid&7;
    float acc[4][4]={};
    for(int kc=0;kc<4;kc++){
        for(int idx=tid;idx<64*32;idx+=256){
            int k=idx>>5,r4=idx&31;
            *(float4*)&Ws[k*128+r4*4]=*(const float4*)&d_WxT[(kc*64+k)*2048+rb*128+r4*4];
        }
        for(int idx=tid;idx<64*8;idx+=256){
            int k=idx>>3,b4=idx&7;
            *(float4*)&Xs[k*32+b4*4]=*(const float4*)&d_XinT[(t*256+kc*64+k)*32+b4*4];
        }
        __syncthreads();
#pragma unroll 8
        for(int k=0;k<64;k++){
            float4 wv=*(float4*)&Ws[k*128+ty*4];
            float4 xv=*(float4*)&Xs[k*32+tx*4];
            acc[0][0]+=wv.x*xv.x;acc[0][1]+=wv.x*xv.y;acc[0][2]+=wv.x*xv.z;acc[0][3]+=wv.x*xv.w;
            acc[1][0]+=wv.y*xv.x;acc[1][1]+=wv.y*xv.y;acc[1][2]+=wv.y*xv.z;acc[1][3]+=wv.y*xv.w;
            acc[2][0]+=wv.z*xv.x;acc[2][1]+=wv.z*xv.y;acc[2][2]+=wv.z*xv.z;acc[2][3]+=wv.z*xv.w;
            acc[3][0]+=wv.w*xv.x;acc[3][1]+=wv.w*xv.y;acc[3][2]+=wv.w*xv.z;acc[3][3]+=wv.w*xv.w;
        }
        __syncthreads();
    }
    int row0=rb*128+ty*4;
#pragma unroll
    for(int i=0;i<4;i++)
        *(float4*)&d_XP[(t*2048+row0+i)*32+tx*4]=make_float4(acc[i][0],acc[i][1],acc[i][2],acc[i][3]);
}

__global__ __launch_bounds__(256) void ntm_loop_kernel(const float* __restrict__ b_lstm,
                                                       const float* __restrict__ b_head){
    extern __shared__ __align__(16) char smraw[];
    float* Ws   =(float*)(smraw);
    float* Xs   =(float*)(smraw+36864);
    float* Ms   =(float*)(smraw+46080);
    float* wrp  =(float*)(smraw+79360);
    float* wwp  =(float*)(smraw+79872);
    float* gs   =(float*)(smraw+80384);   // A2 scratch (512)
    float* sred =(float*)(smraw+80384);   // B1 scratch (768)
    float* ps   =(float*)(smraw+80384);   // B2 transients
    float* kr   =ps+272;
    float* kw   =kr+64;
    float* er   =kw+64;
    float* aw   =er+64;
    float* wcr  =aw+64;
    float* wcw  =wcr+128;
    float* redbuf=wcw+128;
    float* sc   =redbuf+8;
    float* minv =sc+16;

    const int g=blockIdx.x,tid=threadIdx.x;
    unsigned nb=0;
    const int rb=g>>3,kc=g&7;
    const int ty=tid>>3,tx=tid&7;

    // ---- init ----
    {
        int gt=g*256+tid; const int nt=NBLK*256;
        for(int i=gt;i<576*32;i+=nt) d_XT[i]=0.f;
        for(int i=gt;i<512*32;i+=nt) d_cT[i]=0.f;
    }
    // persistent A1 weights, loaded once
    for(int idx=tid;idx<72*32;idx+=256){
        int k=idx>>5,r4=idx&31;
        *(float4*)&Ws[k*128+r4*4]=*(const float4*)&d_WrecT[(kc*72+k)*2048+rb*128+r4*4];
    }
    // persistent NTM state for B2 CTAs
    if(g<32){
        for(int i=tid;i<8192;i+=256) Ms[(i>>6)*65+(i&63)]=0.01f;
        if(tid<128){ float v=(tid==0)?1.f:0.f; wrp[tid]=v; wwp[tid]=v; }
    }
    nb++; gridbar(nb*NBLK);

    for(int t=0;t<256;t++){
        // ===== A1: recurrent GEMM partials (uses h,r of t-1 in d_XT) =====
        {
            for(int idx=tid;idx<72*8;idx+=256){
                int k=idx>>3,b4=idx&7;
                *(float4*)&Xs[k*32+b4*4]=*(const float4*)&d_XT[(kc*72+k)*32+b4*4];
            }
            __syncthreads();
            float acc[4][4]={};
#pragma unroll 4
            for(int k=0;k<72;k++){
                float4 wv=*(float4*)&Ws[k*128+ty*4];
                float4 xv=*(float4*)&Xs[k*32+tx*4];
                acc[0][0]+=wv.x*xv.x;acc[0][1]+=wv.x*xv.y;acc[0][2]+=wv.x*xv.z;acc[0][3]+=wv.x*xv.w;
                acc[1][0]+=wv.y*xv.x;acc[1][1]+=wv.y*xv.y;acc[1][2]+=wv.y*xv.z;acc[1][3]+=wv.y*xv.w;
                acc[2][0]+=wv.z*xv.x;acc[2][1]+=wv.z*xv.y;acc[2][2]+=wv.z*xv.z;acc[2][3]+=wv.z*xv.w;
                acc[3][0]+=wv.w*xv.x;acc[3][1]+=wv.w*xv.y;acc[3][2]+=wv.w*xv.z;acc[3][3]+=wv.w*xv.w;
            }
            int row0=rb*128+ty*4;
#pragma unroll
            for(int i=0;i<4;i++)
                *(float4*)&d_Part[(kc*2048+row0+i)*32+tx*4]=make_float4(acc[i][0],acc[i][1],acc[i][2],acc[i][3]);
            __syncthreads();
        }
        nb++; gridbar(nb*NBLK);

        // ===== A2: reduce + LSTM =====
        {
            int jb=g*4;
            for(int v=tid;v<512;v+=256){
                int q=v>>7,jo=(v>>5)&3,b=v&31;
                int row=q*512+jb+jo;
                float s=b_lstm[row]+d_XP[(t*2048+row)*32+b];
#pragma unroll
                for(int kk=0;kk<8;kk++) s+=d_Part[(kk*2048+row)*32+b];
                gs[v]=s;
            }
            __syncthreads();
            if(tid<128){
                int jo=tid>>5,b=tid&31,j=jb+jo;
                float gi=gs[jo*32+b];
                float gf=gs[128+jo*32+b];
                float gg=gs[256+jo*32+b];
                float go=gs[384+jo*32+b];
                float c=sigmf(gf)*d_cT[j*32+b]+sigmf(gi)*tanhf(gg);
                float h=sigmf(go)*tanhf(c);
                d_cT[j*32+b]=c;
                d_XT[j*32+b]=h;
                d_HR[(t*576+j)*32+b]=h;
            }
            __syncthreads();
        }
        nb++; gridbar(nb*NBLK);

        // ===== B1: head GEMM (distributed over 90 CTAs) =====
        if(g<90){
            int o3=g*3,kg=tid>>5,b=tid&31;
            float a0=0.f,a1=0.f,a2v=0.f;
            for(int k=kg*64;k<kg*64+64;k++){
                float xv=d_XT[k*32+b];
                a0 +=d_WheadT[k*272+o3  ]*xv;
                a1 +=d_WheadT[k*272+o3+1]*xv;
                a2v+=d_WheadT[k*272+o3+2]*xv;
            }
            sred[kg*96+   b]=a0;
            sred[kg*96+32+b]=a1;
            sred[kg*96+64+b]=a2v;
            __syncthreads();
            if(tid<96){
                int m=tid>>5,bb=tid&31,o=o3+m;
                if(o<268){
                    float s=0.f;
#pragma unroll
                    for(int q=0;q<8;q++) s+=sred[q*96+m*32+bb];
                    d_P[o*32+bb]=s;
                }
            }
            __syncthreads();
        }
        nb++; gridbar(nb*NBLK);

        // ===== B2: addressing + memory update + read =====
        if(g<32){
            const int b=g;
            for(int o=tid;o<272;o+=256) ps[o]=(o<268)?(d_P[o*32+b]+b_head[o]):0.f;
            __syncthreads();
            if(tid==0){
                sc[0]=softplusf(ps[64]);
                sc[1]=sigmf(ps[65]);
                float m=fmaxf(ps[66],fmaxf(ps[67],ps[68]));
                float e0=expf(ps[66]-m),e1=expf(ps[67]-m),e2=expf(ps[68]-m);
                float s=e0+e1+e2;
                sc[2]=e0/s;sc[3]=e1/s;sc[4]=e2/s;
                sc[5]=1.f+softplusf(ps[69]);
            }
            if(tid==32){
                sc[6]=softplusf(ps[134]);
                sc[7]=sigmf(ps[135]);
                float m=fmaxf(ps[136],fmaxf(ps[137],ps[138]));
                float e0=expf(ps[136]-m),e1=expf(ps[137]-m),e2=expf(ps[138]-m);
                float s=e0+e1+e2;
                sc[8]=e0/s;sc[9]=e1/s;sc[10]=e2/s;
                sc[11]=1.f+softplusf(ps[139]);
            }
            if(tid==64){
                float s=0.f;
                for(int c=0;c<64;c++){float v=ps[c];s+=v*v;}
                sc[12]=sqrtf(s)+EPSF;
            }
            if(tid==96){
                float s=0.f;
                for(int c=0;c<64;c++){float v=ps[70+c];s+=v*v;}
                sc[13]=sqrtf(s)+EPSF;
            }
            if(tid>=128&&tid<192){
                int c=tid-128;
                kr[c]=ps[c];
                kw[c]=ps[70+c];
                er[c]=sigmf(ps[140+c]);
                aw[c]=ps[204+c];
            }
            __syncthreads();

            const int n=tid&127;
            float myv;
            {
                const float* mr=&Ms[n*65];
                if(tid<128){
                    float m2=0.f,dr=0.f;
                    for(int c=0;c<64;c++){float mv=mr[c];m2+=mv*mv;dr+=mv*kr[c];}
                    float inv=1.f/(sqrtf(m2)+EPSF);
                    minv[n]=inv;
                    myv=sc[0]*dr*inv/sc[12];
                }else{
                    float dw=0.f;
                    for(int c=0;c<64;c++) dw+=mr[c]*kw[c];
                    myv=dw;
                }
            }
            __syncthreads();
            if(tid>=128) myv=sc[6]*myv*minv[n]/sc[13];

            float m=myv;
#pragma unroll
            for(int o=16;o>0;o>>=1) m=fmaxf(m,__shfl_xor_sync(0xffffffffu,m,o));
            if((tid&31)==0) redbuf[tid>>5]=m;
            __syncthreads();
            float h0=fmaxf(fmaxf(redbuf[0],redbuf[1]),fmaxf(redbuf[2],redbuf[3]));
            float h1=fmaxf(fmaxf(redbuf[4],redbuf[5]),fmaxf(redbuf[6],redbuf[7]));
            __syncthreads();
            float ex=expf(myv-((tid<128)?h0:h1));
            float sm2=ex;
#pragma unroll
            for(int o=16;o>0;o>>=1) sm2+=__shfl_xor_sync(0xffffffffu,sm2,o);
            if((tid&31)==0) redbuf[tid>>5]=sm2;
            __syncthreads();
            float s0h=redbuf[0]+redbuf[1]+redbuf[2]+redbuf[3];
            float s1h=redbuf[4]+redbuf[5]+redbuf[6]+redbuf[7];
            float wc=ex/((tid<128)?s0h:s1h);

            float wprev=(tid<128)?wrp[n]:wwp[n];
            float ggate=(tid<128)?sc[1]:sc[7];
            float wg=ggate*wc+(1.f-ggate)*wprev;
            __syncthreads();
            if(tid<128) wcr[n]=wg; else wcw[n]=wg;
            __syncthreads();

            float sA,sB,sC,gam;
            if(tid<128){sA=sc[2];sB=sc[3];sC=sc[4];gam=sc[5];}
            else       {sA=sc[8];sB=sc[9];sC=sc[10];gam=sc[11];}
            const float* WArr=(tid<128)?wcr:wcw;
            float wsv=sA*WArr[(n+1)&127]+sB*WArr[n]+sC*WArr[(n+127)&127];
            float wp=powf(wsv+EPSF,gam);
            __syncthreads();
            float sp=wp;
#pragma unroll
            for(int o=16;o>0;o>>=1) sp+=__shfl_xor_sync(0xffffffffu,sp,o);
            if((tid&31)==0) redbuf[tid>>5]=sp;
            __syncthreads();
            float p0=redbuf[0]+redbuf[1]+redbuf[2]+redbuf[3];
            float p1=redbuf[4]+redbuf[5]+redbuf[6]+redbuf[7];
            float wfin=wp/((tid<128)?p0:p1);
            if(tid<128){wcr[n]=wfin;wrp[n]=wfin;}
            else       {wcw[n]=wfin;wwp[n]=wfin;}
            __syncthreads();

            for(int i=tid;i<8192;i+=256){
                int n2=i>>6,c=i&63;
                float wwn=wcw[n2];
                float mval=Ms[n2*65+c];
                Ms[n2*65+c]=mval*(1.f-wwn*er[c])+wwn*aw[c];
            }
            __syncthreads();
            if(tid<64){
                int c=tid;
                float acc=0.f;
                for(int n2=0;n2<128;n2++) acc+=wcr[n2]*Ms[n2*65+c];
                d_XT[(512+c)*32+b]=acc;
                d_HR[(t*576+512+c)*32+b]=acc;
            }
            __syncthreads();
        }
        nb++; gridbar(nb*NBLK);
    }
}

__global__ __launch_bounds__(256) void out_gemm_kernel(const float* __restrict__ b_out,
                                                       float* __restrict__ out){
    __shared__ __align__(16) float Ws[32*256];
    __shared__ __align__(16) float Xs[32*32];
    int t=blockIdx.x,tid=threadIdx.x;
    int og=tid>>2,bg=tid&3;
    float acc[8][4]={};
    for(int kc=0;kc<18;kc++){
        for(int idx=tid;idx<32*64;idx+=256){
            int k=idx>>6,o4=idx&63;
            *(float4*)&Ws[k*256+o4*4]=*(const float4*)&d_WoutT[(kc*32+k)*256+o4*4];
        }
        for(int idx=tid;idx<32*8;idx+=256){
            int k=idx>>3,b4=idx&7;
            *(float4*)&Xs[k*32+b4*4]=*(const float4*)&d_HR[(t*576+kc*32+k)*32+b4*4];
        }
        __syncthreads();
#pragma unroll 8
        for(int k=0;k<32;k++){
            float4 wv=*(float4*)&Ws[k*256+og*4];
            float4 x0=*(float4*)&Xs[k*32+bg*8];
            float4 x1=*(float4*)&Xs[k*32+bg*8+4];
            acc[0][0]+=x0.x*wv.x;acc[0][1]+=x0.x*wv.y;acc[0][2]+=x0.x*wv.z;acc[0][3]+=x0.x*wv.w;
            acc[1][0]+=x0.y*wv.x;acc[1][1]+=x0.y*wv.y;acc[1][2]+=x0.y*wv.z;acc[1][3]+=x0.y*wv.w;
            acc[2][0]+=x0.z*wv.x;acc[2][1]+=x0.z*wv.y;acc[2][2]+=x0.z*wv.z;acc[2][3]+=x0.z*wv.w;
            acc[3][0]+=x0.w*wv.x;acc[3][1]+=x0.w*wv.y;acc[3][2]+=x0.w*wv.z;acc[3][3]+=x0.w*wv.w;
            acc[4][0]+=x1.x*wv.x;acc[4][1]+=x1.x*wv.y;acc[4][2]+=x1.x*wv.z;acc[4][3]+=x1.x*wv.w;
            acc[5][0]+=x1.y*wv.x;acc[5][1]+=x1.y*wv.y;acc[5][2]+=x1.y*wv.z;acc[5][3]+=x1.y*wv.w;
            acc[6][0]+=x1.z*wv.x;acc[6][1]+=x1.z*wv.y;acc[6][2]+=x1.z*wv.z;acc[6][3]+=x1.z*wv.w;
            acc[7][0]+=x1.w*wv.x;acc[7][1]+=x1.w*wv.y;acc[7][2]+=x1.w*wv.z;acc[7][3]+=x1.w*wv.w;
        }
        __syncthreads();
    }
    int o0=og*4;
    float4 bias=*(const float4*)&b_out[o0];
#pragma unroll
    for(int bb=0;bb<8;bb++){
        int b=bg*8+bb;
        *(float4*)&out[(b*256+t)*256+o0]=make_float4(acc[bb][0]+bias.x,acc[bb][1]+bias.y,
                                                     acc[bb][2]+bias.z,acc[bb][3]+bias.w);
    }
}

extern "C" void kernel_launch(void* const* d_in, const int* in_sizes, int n_in,
                              void* d_out, int out_size){
    const float* x     =(const float*)d_in[0];
    const float* W_ih  =(const float*)d_in[1];
    const float* W_hh  =(const float*)d_in[2];
    const float* b_lstm=(const float*)d_in[3];
    const float* W_head=(const float*)d_in[4];
    const float* b_head=(const float*)d_in[5];
    const float* W_out =(const float*)d_in[6];
    const float* b_out =(const float*)d_in[7];
    float* out=(float*)d_out;

    static int smem_set=0;
    if(!smem_set){
        cudaFuncSetAttribute(ntm_loop_kernel, cudaFuncAttributeMaxDynamicSharedMemorySize, SMEM_BYTES);
        smem_set=1;
    }

    prep_kernel<<<148,256>>>(W_ih,W_hh,W_head,W_out);
    tin_kernel<<<dim3(8,256),256>>>(x);
    xp_gemm_kernel<<<dim3(16,256),256>>>();
    ntm_loop_kernel<<<NBLK,256,SMEM_BYTES>>>(b_lstm,b_head);
    out_gemm_kernel<<<256,256>>>(b_out,out);
}